// round 1
// baseline (speedup 1.0000x reference)
#include <cuda_runtime.h>

#define LOG2E 1.4426950408889634f
#define N_EN 20000
#define M_MEN 256
#define TN 64   // entities per block (threadIdx.x)
#define MG 4    // mention-groups per block (threadIdx.y)
#define RM 8    // mentions per thread

static __device__ float g_Gm[M_MEN];

__device__ __forceinline__ float ex2f(float x) {
    float r; asm("ex2.approx.ftz.f32 %0, %1;" : "=f"(r) : "f"(x)); return r;
}
__device__ __forceinline__ float lg2f(float x) {
    float r; asm("lg2.approx.ftz.f32 %0, %1;" : "=f"(r) : "f"(x)); return r;
}

// Per-mention log2-volume: Gm[m] = sum_d lg2( lg2(1 + 2^{(Z-z)*log2e}) )
// (same approximation path as the main kernel so errors partially cancel)
__global__ void gm_kernel(const float* __restrict__ men) {
    int m = threadIdx.x;
    const float* row = men + m * 128;
    float acc = 0.f;
#pragma unroll
    for (int c = 0; c < 8; ++c) {
        float prod = 1.f;
#pragma unroll
        for (int k = 0; k < 8; ++k) {
            int d = c * 8 + k;
            float x = (row[64 + d] - row[d]) * LOG2E;
            prod *= lg2f(1.f + ex2f(x));
        }
        acc += lg2f(prod);
    }
    g_Gm[m] = acc;
}

// out[m,n] = 2^( G[m,n] - Gm[m] )
// G[m,n] = sum_{chunks c} lg2( prod_{k} lg2(1 + 2^{hi-lo}) ), inputs pre-scaled by log2e.
__global__ __launch_bounds__(256) void ivr_kernel(const float* __restrict__ men,
                                                  const float* __restrict__ en,
                                                  float* __restrict__ out) {
    __shared__ float s_men[32][128];   // 32 mentions x 128 floats, prescaled by log2e

    const int tid = threadIdx.y * TN + threadIdx.x;
    const int m0  = blockIdx.y * 32;
#pragma unroll
    for (int i = 0; i < 16; ++i) {
        int idx = tid + i * 256;
        s_men[idx >> 7][idx & 127] = men[m0 * 128 + idx] * LOG2E;
    }
    __syncthreads();

    const int n = blockIdx.x * TN + threadIdx.x;
    if (n >= N_EN) return;

    const int mg = threadIdx.y;
    float acc[RM];
#pragma unroll
    for (int j = 0; j < RM; ++j) acc[j] = 0.f;

    const float* erow = en + (size_t)n * 128;

#pragma unroll
    for (int c = 0; c < 8; ++c) {
        float ez[8], eZ[8];
        float4 a0 = *(const float4*)(erow + c * 8);
        float4 a1 = *(const float4*)(erow + c * 8 + 4);
        float4 b0 = *(const float4*)(erow + 64 + c * 8);
        float4 b1 = *(const float4*)(erow + 64 + c * 8 + 4);
        ez[0] = a0.x * LOG2E; ez[1] = a0.y * LOG2E; ez[2] = a0.z * LOG2E; ez[3] = a0.w * LOG2E;
        ez[4] = a1.x * LOG2E; ez[5] = a1.y * LOG2E; ez[6] = a1.z * LOG2E; ez[7] = a1.w * LOG2E;
        eZ[0] = b0.x * LOG2E; eZ[1] = b0.y * LOG2E; eZ[2] = b0.z * LOG2E; eZ[3] = b0.w * LOG2E;
        eZ[4] = b1.x * LOG2E; eZ[5] = b1.y * LOG2E; eZ[6] = b1.z * LOG2E; eZ[7] = b1.w * LOG2E;

#pragma unroll
        for (int j = 0; j < RM; ++j) {
            const float* mrow = s_men[mg * RM + j];
            float prod = 1.f;
#pragma unroll
            for (int k = 0; k < 8; ++k) {
                float lo = fmaxf(mrow[c * 8 + k], ez[k]);        // smem broadcast
                float hi = fminf(mrow[64 + c * 8 + k], eZ[k]);
                prod *= lg2f(1.f + ex2f(hi - lo));               // 2 MUFU / element
            }
            acc[j] += lg2f(prod);                                 // 1 MUFU / 8 elements
        }
    }

#pragma unroll
    for (int j = 0; j < RM; ++j) {
        int m = m0 + mg * RM + j;
        out[(size_t)m * N_EN + n] = ex2f(acc[j] - g_Gm[m]);       // coalesced over n
    }
}

extern "C" void kernel_launch(void* const* d_in, const int* in_sizes, int n_in,
                              void* d_out, int out_size) {
    const float* men = (const float*)d_in[0];
    const float* en  = (const float*)d_in[1];
    // defensive: men_embeds is the small tensor (256*128 = 32768 elems)
    if (n_in >= 2 && in_sizes[0] > in_sizes[1]) {
        const float* t = men; men = en; en = t;
    }
    float* out = (float*)d_out;

    gm_kernel<<<1, 256>>>(men);

    dim3 block(TN, MG);
    dim3 grid((N_EN + TN - 1) / TN, M_MEN / (MG * RM));
    ivr_kernel<<<grid, block>>>(men, en, out);
}

// round 2
// speedup vs baseline: 1.0699x; 1.0699x over previous
#include <cuda_runtime.h>

#define LOG2E 1.4426950408889634f
#define N_EN  20000
#define M_MEN 256
#define TN 64   // entities per block (threadIdx.x)
#define MG 4    // mention-groups per block (threadIdx.y)
#define RM 8    // mentions per thread

typedef unsigned long long ull;

__device__ __forceinline__ float ex2f(float x){float r;asm("ex2.approx.ftz.f32 %0,%1;":"=f"(r):"f"(x));return r;}
__device__ __forceinline__ float lg2f(float x){float r;asm("lg2.approx.ftz.f32 %0,%1;":"=f"(r):"f"(x));return r;}

__device__ __forceinline__ ull pk(float a,float b){ull r;asm("mov.b64 %0,{%1,%2};":"=l"(r):"f"(a),"f"(b));return r;}
__device__ __forceinline__ void upk(ull v,float&a,float&b){asm("mov.b64 {%0,%1},%2;":"=f"(a),"=f"(b):"l"(v));}
__device__ __forceinline__ ull ffma2(ull a,ull b,ull c){ull r;asm("fma.rn.f32x2 %0,%1,%2,%3;":"=l"(r):"l"(a),"l"(b),"l"(c));return r;}
__device__ __forceinline__ ull fmul2(ull a,ull b){ull r;asm("mul.rn.f32x2 %0,%1,%2;":"=l"(r):"l"(a),"l"(b));return r;}

// Degree-6 poly for ln(1+t), t in [0,1], from closed-form Chebyshev series
// (z = 3-2*sqrt(2)); verified G(0)=2.66e-6, G(0.5)=ln1.5, G(1)=ln2.
struct PolyC { ull b6,b5,b4,b3,b2,b1,b0,ln2; };

// s = softplus(x) in nats for a pair of elements; y = x*log2e.
// s = relu(y)*ln2 + G(2^-|y|); G > 0 always => s > 0 (no NaN downstream).
__device__ __forceinline__ ull sp_pair(float y0, float y1, const PolyC& C){
    float t0 = ex2f(-fabsf(y0));
    float t1 = ex2f(-fabsf(y1));
    float r0 = fmaxf(y0, 0.f);
    float r1 = fmaxf(y1, 0.f);
    ull tv = pk(t0,t1);
    ull rv = pk(r0,r1);
    ull p = ffma2(C.b6, tv, C.b5);
    p = ffma2(p, tv, C.b4);
    p = ffma2(p, tv, C.b3);
    p = ffma2(p, tv, C.b2);
    p = ffma2(p, tv, C.b1);
    p = ffma2(p, tv, C.b0);      // G(t)
    return ffma2(rv, C.ln2, p);  // s = relu*ln2 + G
}

// lg2 of product of 8 softplus values for one chunk.
// mz/mZ: mention mins/maxs (prescaled by log2e), ez/eZ: entity (prescaled).
__device__ __forceinline__ float chunk_lg2(const float* mz, const float* mZ,
                                           const float* ez, const float* eZ,
                                           const PolyC& C){
    ull prod = 0;
#pragma unroll
    for (int p = 0; p < 4; ++p){
        float y0 = fminf(mZ[2*p],   eZ[2*p])   - fmaxf(mz[2*p],   ez[2*p]);
        float y1 = fminf(mZ[2*p+1], eZ[2*p+1]) - fmaxf(mz[2*p+1], ez[2*p+1]);
        ull s = sp_pair(y0, y1, C);
        prod = p ? fmul2(prod, s) : s;
    }
    float pa, pb; upk(prod, pa, pb);
    return lg2f(pa * pb);
}

__global__ __launch_bounds__(256, 3) void ivr_kernel(const float* __restrict__ men,
                                                     const float* __restrict__ en,
                                                     float* __restrict__ out){
    __shared__ float s_men[32][128];     // 32 mentions, prescaled by log2e
    __shared__ float s_gmp[256];         // per-(mention,chunk) gm partials
    __shared__ float s_gm[32];           // per-mention log2 self-volume

    PolyC C;
    C.b6 = pk(-0.017415424f, -0.017415424f);
    C.b5 = pk( 0.08269552f,   0.08269552f);
    C.b4 = pk(-0.190359232f, -0.190359232f);
    C.b3 = pk( 0.31574968f,   0.31574968f);
    C.b2 = pk(-0.497373624f, -0.497373624f);
    C.b1 = pk( 0.9998477f,    0.9998477f);
    C.b0 = pk( 2.66e-6f,      2.66e-6f);
    C.ln2= pk( 0.69314718f,   0.69314718f);

    const int tid = threadIdx.y * TN + threadIdx.x;
    const int m0  = blockIdx.y * 32;

#pragma unroll
    for (int i = 0; i < 16; ++i){
        int idx = tid + i * 256;
        s_men[idx >> 7][idx & 127] = men[m0 * 128 + idx] * LOG2E;
    }
    __syncthreads();

    // --- per-mention self volume, same value path as main loop ---
    {
        int mi = tid >> 3, ci = tid & 7;
        float mzv[8], mZv[8];
        const float4* lo4 = (const float4*)(&s_men[mi][ci*8]);
        const float4* hi4 = (const float4*)(&s_men[mi][64 + ci*8]);
        float4 a0 = lo4[0], a1 = lo4[1], b0 = hi4[0], b1 = hi4[1];
        mzv[0]=a0.x; mzv[1]=a0.y; mzv[2]=a0.z; mzv[3]=a0.w;
        mzv[4]=a1.x; mzv[5]=a1.y; mzv[6]=a1.z; mzv[7]=a1.w;
        mZv[0]=b0.x; mZv[1]=b0.y; mZv[2]=b0.z; mZv[3]=b0.w;
        mZv[4]=b1.x; mZv[5]=b1.y; mZv[6]=b1.z; mZv[7]=b1.w;
        s_gmp[tid] = chunk_lg2(mzv, mZv, mzv, mZv, C);
    }
    __syncthreads();
    if (tid < 32){
        float s = 0.f;
#pragma unroll
        for (int i = 0; i < 8; ++i) s += s_gmp[tid*8 + i];
        s_gm[tid] = s;
    }
    __syncthreads();

    const int n  = blockIdx.x * TN + threadIdx.x;
    const int nn = n < N_EN ? n : (N_EN - 1);   // clamp for safe loads; no early return
    const int mg = threadIdx.y;

    float acc[RM];
#pragma unroll
    for (int j = 0; j < RM; ++j) acc[j] = 0.f;

    const float* erow = en + (size_t)nn * 128;

#pragma unroll 1
    for (int c = 0; c < 8; ++c){
        float ez[8], eZ[8];
        float4 a0 = *(const float4*)(erow + c*8);
        float4 a1 = *(const float4*)(erow + c*8 + 4);
        float4 b0 = *(const float4*)(erow + 64 + c*8);
        float4 b1 = *(const float4*)(erow + 64 + c*8 + 4);
        ez[0]=a0.x*LOG2E; ez[1]=a0.y*LOG2E; ez[2]=a0.z*LOG2E; ez[3]=a0.w*LOG2E;
        ez[4]=a1.x*LOG2E; ez[5]=a1.y*LOG2E; ez[6]=a1.z*LOG2E; ez[7]=a1.w*LOG2E;
        eZ[0]=b0.x*LOG2E; eZ[1]=b0.y*LOG2E; eZ[2]=b0.z*LOG2E; eZ[3]=b0.w*LOG2E;
        eZ[4]=b1.x*LOG2E; eZ[5]=b1.y*LOG2E; eZ[6]=b1.z*LOG2E; eZ[7]=b1.w*LOG2E;

#pragma unroll
        for (int j = 0; j < RM; ++j){
            float mzv[8], mZv[8];
            const float4* lo4 = (const float4*)(&s_men[mg*RM + j][c*8]);
            const float4* hi4 = (const float4*)(&s_men[mg*RM + j][64 + c*8]);
            float4 ma0 = lo4[0], ma1 = lo4[1], mb0 = hi4[0], mb1 = hi4[1];
            mzv[0]=ma0.x; mzv[1]=ma0.y; mzv[2]=ma0.z; mzv[3]=ma0.w;
            mzv[4]=ma1.x; mzv[5]=ma1.y; mzv[6]=ma1.z; mzv[7]=ma1.w;
            mZv[0]=mb0.x; mZv[1]=mb0.y; mZv[2]=mb0.z; mZv[3]=mb0.w;
            mZv[4]=mb1.x; mZv[5]=mb1.y; mZv[6]=mb1.z; mZv[7]=mb1.w;
            acc[j] += chunk_lg2(mzv, mZv, ez, eZ, C);
        }
    }

    if (n < N_EN){
#pragma unroll
        for (int j = 0; j < RM; ++j){
            int m = m0 + mg*RM + j;
            out[(size_t)m * N_EN + n] = ex2f(acc[j] - s_gm[mg*RM + j]);
        }
    }
}

extern "C" void kernel_launch(void* const* d_in, const int* in_sizes, int n_in,
                              void* d_out, int out_size){
    const float* men = (const float*)d_in[0];
    const float* en  = (const float*)d_in[1];
    if (n_in >= 2 && in_sizes[0] > in_sizes[1]){
        const float* t = men; men = en; en = t;
    }
    float* out = (float*)d_out;

    dim3 block(TN, MG);
    dim3 grid((N_EN + TN - 1) / TN, M_MEN / (MG * RM));
    ivr_kernel<<<grid, block>>>(men, en, out);
}